// round 1
// baseline (speedup 1.0000x reference)
#include <cuda_runtime.h>
#include <math.h>

// RewardModel: only rewards[b, last[b]] are consumed, so we never compute the
// full [B,S,H]@[H] matvecs. Per batch row: find the score index from the id
// scans, then do two H-length dot products.
//
// Inputs (metadata order):
//   0: chosen_ids      int32  [B,S]
//   1: chosen_mask     int32  [B,S]
//   2: rejected_ids    int32  [B,S]
//   3: chosen_hidden   fp32   [B,S,H]
//   4: rejected_hidden fp32   [B,S,H]
//   5: v_head_w        fp32   [H]
// Output: fp32 [1 + 2B] = [loss, chosen_mean_scores(B), rejected_mean_scores(B)]

#define NT 256

__device__ __forceinline__ float block_reduce_sum(float v, float* sh) {
    // warp reduce
    #pragma unroll
    for (int o = 16; o; o >>= 1) v += __shfl_down_sync(0xffffffffu, v, o);
    const int warp = threadIdx.x >> 5;
    const int lane = threadIdx.x & 31;
    if (lane == 0) sh[warp] = v;
    __syncthreads();
    float r = 0.f;
    if (warp == 0) {
        r = (lane < (NT >> 5)) ? sh[lane] : 0.f;
        #pragma unroll
        for (int o = 4; o; o >>= 1) r += __shfl_down_sync(0xffffffffu, r, o);
    }
    return r;  // valid in thread 0 only
}

__global__ __launch_bounds__(NT)
void reward_scores_kernel(const int* __restrict__ chosen_ids,
                          const int* __restrict__ chosen_mask,
                          const int* __restrict__ rejected_ids,
                          const float* __restrict__ chosen_hidden,
                          const float* __restrict__ rejected_hidden,
                          const float* __restrict__ v_head_w,
                          float* __restrict__ out,
                          int B, int S, int H) {
    const int b   = blockIdx.x;
    const int tid = threadIdx.x;

    const int* cid = chosen_ids   + (size_t)b * S;
    const int* msk = chosen_mask  + (size_t)b * S;
    const int* rid = rejected_ids + (size_t)b * S;

    __shared__ int   s_imin[NT];
    __shared__ int   s_bcast[3];
    __shared__ float s_f[NT >> 5];

    // ---- pass 1: start_ind = first s with mask != 0 (default 0) ----
    int ls = S;
    if ((S & 3) == 0) {
        for (int s4 = tid * 4; s4 < S; s4 += NT * 4) {
            int4 m = *(const int4*)(msk + s4);
            if (m.x) { ls = s4;     break; }
            if (m.y) { ls = s4 + 1; break; }
            if (m.z) { ls = s4 + 2; break; }
            if (m.w) { ls = s4 + 3; break; }
        }
    } else {
        for (int s = tid; s < S; s += NT)
            if (msk[s]) { ls = s; break; }   // strided ascending -> first hit is thread min
    }
    s_imin[tid] = ls;
    __syncthreads();
    #pragma unroll
    for (int off = NT / 2; off; off >>= 1) {
        if (tid < off) s_imin[tid] = min(s_imin[tid], s_imin[tid + off]);
        __syncthreads();
    }
    if (tid == 0) s_bcast[0] = (s_imin[0] == S) ? 0 : s_imin[0];
    __syncthreads();
    const int start = s_bcast[0];

    // ---- pass 2: c_ind, r_ind_div (first PAD==0 at s>=start, default S), has_div ----
    int lc = S, lr = S, ldiv = 0;
    if ((S & 3) == 0) {
        for (int s4 = tid * 4; s4 < S; s4 += NT * 4) {
            int4 c = *(const int4*)(cid + s4);
            int4 r = *(const int4*)(rid + s4);
            ldiv |= (c.x != r.x) | (c.y != r.y) | (c.z != r.z) | (c.w != r.w);
            if (c.x == 0 && s4 + 0 >= start && s4 + 0 < lc) lc = s4 + 0;
            if (c.y == 0 && s4 + 1 >= start && s4 + 1 < lc) lc = s4 + 1;
            if (c.z == 0 && s4 + 2 >= start && s4 + 2 < lc) lc = s4 + 2;
            if (c.w == 0 && s4 + 3 >= start && s4 + 3 < lc) lc = s4 + 3;
            if (r.x == 0 && s4 + 0 >= start && s4 + 0 < lr) lr = s4 + 0;
            if (r.y == 0 && s4 + 1 >= start && s4 + 1 < lr) lr = s4 + 1;
            if (r.z == 0 && s4 + 2 >= start && s4 + 2 < lr) lr = s4 + 2;
            if (r.w == 0 && s4 + 3 >= start && s4 + 3 < lr) lr = s4 + 3;
        }
    } else {
        for (int s = tid; s < S; s += NT) {
            int c = cid[s], r = rid[s];
            ldiv |= (c != r);
            if (s >= start) {
                if (c == 0 && s < lc) lc = s;
                if (r == 0 && s < lr) lr = s;
            }
        }
    }
    const int hasdiv = __syncthreads_or(ldiv);

    s_imin[tid] = lc;
    __syncthreads();
    #pragma unroll
    for (int off = NT / 2; off; off >>= 1) {
        if (tid < off) s_imin[tid] = min(s_imin[tid], s_imin[tid + off]);
        __syncthreads();
    }
    if (tid == 0) s_bcast[1] = s_imin[0];
    __syncthreads();

    s_imin[tid] = lr;
    __syncthreads();
    #pragma unroll
    for (int off = NT / 2; off; off >>= 1) {
        if (tid < off) s_imin[tid] = min(s_imin[tid], s_imin[tid + off]);
        __syncthreads();
    }
    if (tid == 0) s_bcast[2] = s_imin[0];
    __syncthreads();

    const int c_ind = s_bcast[1];
    const int r_ind = hasdiv ? s_bcast[2] : c_ind;  // no-div branch: min(c_ind, S) == c_ind
    int last = min(c_ind, r_ind) - 1;
    if (last < 0) last += S;  // JAX dynamic negative-index wrap

    // ---- dot products at the score position ----
    const float* ch = chosen_hidden   + ((size_t)b * S + last) * H;
    const float* rh = rejected_hidden + ((size_t)b * S + last) * H;

    float ac = 0.f, ar = 0.f;
    if ((H & 3) == 0) {
        for (int h = tid * 4; h < H; h += NT * 4) {
            float4 w  = *(const float4*)(v_head_w + h);
            float4 c4 = *(const float4*)(ch + h);
            float4 r4 = *(const float4*)(rh + h);
            ac += c4.x * w.x + c4.y * w.y + c4.z * w.z + c4.w * w.w;
            ar += r4.x * w.x + r4.y * w.y + r4.z * w.z + r4.w * w.w;
        }
    } else {
        for (int h = tid; h < H; h += NT) {
            float w = v_head_w[h];
            ac += ch[h] * w;
            ar += rh[h] * w;
        }
    }

    float cs = block_reduce_sum(ac, s_f);
    __syncthreads();
    float rs = block_reduce_sum(ar, s_f);
    if (tid == 0) {
        out[1 + b]     = cs;
        out[1 + B + b] = rs;
    }
}

__global__ void loss_kernel(float* __restrict__ out, int B) {
    const int t = threadIdx.x;  // one warp
    float v = 0.f;
    for (int i = t; i < B; i += 32) {
        float d = out[1 + i] - out[1 + B + i];
        // -log_sigmoid(d) = softplus(-d), numerically stable
        v += fmaxf(-d, 0.f) + log1pf(expf(-fabsf(d)));
    }
    #pragma unroll
    for (int o = 16; o; o >>= 1) v += __shfl_down_sync(0xffffffffu, v, o);
    if (t == 0) out[0] = v / (float)B;
}

extern "C" void kernel_launch(void* const* d_in, const int* in_sizes, int n_in,
                              void* d_out, int out_size) {
    const int*   chosen_ids      = (const int*)  d_in[0];
    const int*   chosen_mask     = (const int*)  d_in[1];
    const int*   rejected_ids    = (const int*)  d_in[2];
    const float* chosen_hidden   = (const float*)d_in[3];
    const float* rejected_hidden = (const float*)d_in[4];
    const float* v_head_w        = (const float*)d_in[5];
    float*       out             = (float*)d_out;

    const int B = (out_size - 1) / 2;          // out = [loss, chosen(B), rejected(B)]
    const int S = in_sizes[0] / B;             // chosen_ids is [B,S]
    const int H = in_sizes[5];                 // v_head_w is [H]

    reward_scores_kernel<<<B, NT>>>(chosen_ids, chosen_mask, rejected_ids,
                                    chosen_hidden, rejected_hidden, v_head_w,
                                    out, B, S, H);
    loss_kernel<<<1, 32>>>(out, B);
}

// round 2
// speedup vs baseline: 1.0036x; 1.0036x over previous
#include <cuda_runtime.h>
#include <math.h>
#include <limits.h>

// RewardModel fused kernel: only rewards[b, last[b]] are consumed, so we never
// materialize the [B,S,H]@[H] matvecs. One block per batch row:
//   1. one front-batched load burst of mask/chosen/rejected ids (registers)
//   2. start = first nonzero mask; c_ind/r_ind = first PAD >= start; has_div
//   3. last = min(c_ind, r_ind) - 1  (JAX negative-index wrap)
//   4. two H-length dot products at row `last`
//   5. last-arriving block computes the mean softplus loss (no 2nd launch)
//
// Inputs (metadata order):
//   0: chosen_ids int32 [B,S]   1: chosen_mask int32 [B,S]
//   2: rejected_ids int32 [B,S] 3: chosen_hidden fp32 [B,S,H]
//   4: rejected_hidden fp32 [B,S,H]  5: v_head_w fp32 [H]
// Output: fp32 [1 + 2B] = [loss, chosen_scores(B), rejected_scores(B)]

#define NT 512
#define MAXK 4   // fast path covers S <= NT*4*MAXK = 8192

__device__ int g_arrive;   // zero-init; always reset to 0 by the finishing block

__device__ __forceinline__ int block_min_int(int v, int* sh) {
    const int warp = threadIdx.x >> 5, lane = threadIdx.x & 31;
    v = __reduce_min_sync(0xffffffffu, v);
    __syncthreads();                       // protect sh reuse across calls
    if (lane == 0) sh[warp] = v;
    __syncthreads();
    if (warp == 0) {
        int x = (lane < (NT >> 5)) ? sh[lane] : INT_MAX;
        x = __reduce_min_sync(0xffffffffu, x);
        if (lane == 0) sh[0] = x;
    }
    __syncthreads();
    return sh[0];
}

__global__ __launch_bounds__(NT)
void reward_fused_kernel(const int* __restrict__ chosen_ids,
                         const int* __restrict__ chosen_mask,
                         const int* __restrict__ rejected_ids,
                         const float* __restrict__ chosen_hidden,
                         const float* __restrict__ rejected_hidden,
                         const float* __restrict__ v_head_w,
                         float* __restrict__ out,
                         int B, int S, int H) {
    const int b   = blockIdx.x;
    const int tid = threadIdx.x;

    const int* cid = chosen_ids   + (size_t)b * S;
    const int* msk = chosen_mask  + (size_t)b * S;
    const int* rid = rejected_ids + (size_t)b * S;

    __shared__ int   sh_i[NT >> 5];
    __shared__ float sh_f[NT >> 5];
    __shared__ int   sh_last_flag;

    const int K = S / (NT * 4);
    const bool fast = ((S & (NT * 4 - 1)) == 0) && (K <= MAXK);

    int lc = S, lr = S, ldiv = 0;
    int start;

    if (fast) {
        // ---- one load burst: all three arrays into registers ----
        int4 mv[MAXK], cv[MAXK], rv[MAXK];
        #pragma unroll
        for (int k = 0; k < MAXK; k++) {
            if (k < K) {
                const int off = k * NT * 4 + tid * 4;
                mv[k] = *(const int4*)(msk + off);
                cv[k] = *(const int4*)(cid + off);
                rv[k] = *(const int4*)(rid + off);
            }
        }
        // first nonzero mask (descending assignment -> min index wins)
        int ls = S;
        #pragma unroll
        for (int k = MAXK - 1; k >= 0; k--) {
            if (k < K) {
                const int off = k * NT * 4 + tid * 4;
                if (mv[k].w) ls = off + 3;
                if (mv[k].z) ls = off + 2;
                if (mv[k].y) ls = off + 1;
                if (mv[k].x) ls = off;
            }
        }
        start = block_min_int(ls, sh_i);
        if (start == S) start = 0;         // argmax of all-false -> 0

        // first PAD (== 0) at position >= start, for both sequences; divergence flag
        #pragma unroll
        for (int k = MAXK - 1; k >= 0; k--) {
            if (k < K) {
                const int off = k * NT * 4 + tid * 4;
                ldiv |= (cv[k].x != rv[k].x) | (cv[k].y != rv[k].y) |
                        (cv[k].z != rv[k].z) | (cv[k].w != rv[k].w);
                if (cv[k].w == 0 && off + 3 >= start) lc = off + 3;
                if (cv[k].z == 0 && off + 2 >= start) lc = off + 2;
                if (cv[k].y == 0 && off + 1 >= start) lc = off + 1;
                if (cv[k].x == 0 && off     >= start) lc = off;
                if (rv[k].w == 0 && off + 3 >= start) lr = off + 3;
                if (rv[k].z == 0 && off + 2 >= start) lr = off + 2;
                if (rv[k].y == 0 && off + 1 >= start) lr = off + 1;
                if (rv[k].x == 0 && off     >= start) lr = off;
            }
        }
    } else {
        // ---- generic fallback ----
        int ls = S;
        for (int s = tid; s < S; s += NT)
            if (msk[s]) { ls = s; break; }   // strided ascending -> first hit is min
        start = block_min_int(ls, sh_i);
        if (start == S) start = 0;

        for (int s = tid; s < S; s += NT) {
            const int c = cid[s], r = rid[s];
            ldiv |= (c != r);
            if (s >= start) {
                if (c == 0 && s < lc) lc = s;
                if (r == 0 && s < lr) lr = s;
            }
        }
    }

    const int hasdiv = __syncthreads_or(ldiv);
    const int c_ind  = block_min_int(lc, sh_i);
    const int r_divi = block_min_int(lr, sh_i);
    const int r_ind  = hasdiv ? r_divi : c_ind;  // no-div: min(c_ind, S) == c_ind
    int last = min(c_ind, r_ind) - 1;
    if (last < 0) last += S;                      // JAX negative-index wrap

    // ---- dot products at the score position ----
    const float* ch = chosen_hidden   + ((size_t)b * S + last) * H;
    const float* rh = rejected_hidden + ((size_t)b * S + last) * H;

    float ac = 0.f, ar = 0.f;
    if ((H & 3) == 0) {
        for (int h = tid * 4; h < H; h += NT * 4) {
            const float4 w  = *(const float4*)(v_head_w + h);
            const float4 c4 = *(const float4*)(ch + h);
            const float4 r4 = *(const float4*)(rh + h);
            ac += c4.x * w.x + c4.y * w.y + c4.z * w.z + c4.w * w.w;
            ar += r4.x * w.x + r4.y * w.y + r4.z * w.z + r4.w * w.w;
        }
    } else {
        for (int h = tid; h < H; h += NT) {
            const float w = v_head_w[h];
            ac += ch[h] * w;
            ar += rh[h] * w;
        }
    }

    // block reduce both sums (warp shuffle + shared)
    #pragma unroll
    for (int o = 16; o; o >>= 1) {
        ac += __shfl_down_sync(0xffffffffu, ac, o);
        ar += __shfl_down_sync(0xffffffffu, ar, o);
    }
    const int warp = tid >> 5, lane = tid & 31;
    __shared__ float sh_f2[NT >> 5];
    __syncthreads();
    if (lane == 0) { sh_f[warp] = ac; sh_f2[warp] = ar; }
    __syncthreads();
    if (warp == 0) {
        float xc = (lane < (NT >> 5)) ? sh_f[lane]  : 0.f;
        float xr = (lane < (NT >> 5)) ? sh_f2[lane] : 0.f;
        #pragma unroll
        for (int o = 8; o; o >>= 1) {
            xc += __shfl_down_sync(0xffffffffu, xc, o);
            xr += __shfl_down_sync(0xffffffffu, xr, o);
        }
        if (lane == 0) {
            out[1 + b]     = xc;
            out[1 + B + b] = xr;
        }
    }

    // ---- arrival: last block computes the loss (no 2nd launch) ----
    if (tid == 0) {
        __threadfence();
        const int ticket = atomicAdd(&g_arrive, 1);
        sh_last_flag = (ticket == (int)gridDim.x - 1);
    }
    __syncthreads();
    if (sh_last_flag && tid < 32) {
        __threadfence();
        float v = 0.f;
        for (int i = tid; i < B; i += 32) {
            const float c = ((volatile float*)out)[1 + i];
            const float r = ((volatile float*)out)[1 + B + i];
            const float d = c - r;
            // -log_sigmoid(d) = softplus(-d), numerically stable
            v += fmaxf(-d, 0.f) + log1pf(expf(-fabsf(d)));
        }
        #pragma unroll
        for (int o = 16; o; o >>= 1) v += __shfl_down_sync(0xffffffffu, v, o);
        if (tid == 0) {
            out[0] = v / (float)B;
            atomicExch(&g_arrive, 0);   // reset for next graph replay
        }
    }
}

extern "C" void kernel_launch(void* const* d_in, const int* in_sizes, int n_in,
                              void* d_out, int out_size) {
    const int*   chosen_ids      = (const int*)  d_in[0];
    const int*   chosen_mask     = (const int*)  d_in[1];
    const int*   rejected_ids    = (const int*)  d_in[2];
    const float* chosen_hidden   = (const float*)d_in[3];
    const float* rejected_hidden = (const float*)d_in[4];
    const float* v_head_w        = (const float*)d_in[5];
    float*       out             = (float*)d_out;

    const int B = (out_size - 1) / 2;   // out = [loss, chosen(B), rejected(B)]
    const int S = in_sizes[0] / B;      // chosen_ids is [B,S]
    const int H = in_sizes[5];          // v_head_w is [H]

    reward_fused_kernel<<<B, NT>>>(chosen_ids, chosen_mask, rejected_ids,
                                   chosen_hidden, rejected_hidden, v_head_w,
                                   out, B, S, H);
}

// round 3
// speedup vs baseline: 1.0409x; 1.0372x over previous
#include <cuda_runtime.h>
#include <math.h>
#include <limits.h>

// RewardModel fused kernel: only rewards[b, last[b]] are consumed, so we never
// materialize the [B,S,H]@[H] matvecs. One block per batch row:
//   1. one front-batched load burst of mask/chosen/rejected ids (registers)
//   2. start = first nonzero mask; c_ind/r_ind = first PAD >= start; has_div
//   3. last = min(c_ind, r_ind) - 1  (JAX negative-index wrap)
//   4. two H-length dot products at row `last`
//   5. last-arriving block computes the mean softplus loss (no 2nd launch)
//
// Inputs (metadata order):
//   0: chosen_ids int32 [B,S]   1: chosen_mask int32 [B,S]
//   2: rejected_ids int32 [B,S] 3: chosen_hidden fp32 [B,S,H]
//   4: rejected_hidden fp32 [B,S,H]  5: v_head_w fp32 [H]
// Output: fp32 [1 + 2B] = [loss, chosen_scores(B), rejected_scores(B)]

#define NT 512
#define MAXK 4   // fast path covers S <= NT*4*MAXK = 8192

__device__ int g_arrive;   // zero-init; always reset to 0 by the finishing block

__device__ __forceinline__ int block_min_int(int v, int* sh) {
    const int warp = threadIdx.x >> 5, lane = threadIdx.x & 31;
    v = __reduce_min_sync(0xffffffffu, v);
    __syncthreads();                       // protect sh reuse across calls
    if (lane == 0) sh[warp] = v;
    __syncthreads();
    if (warp == 0) {
        int x = (lane < (NT >> 5)) ? sh[lane] : INT_MAX;
        x = __reduce_min_sync(0xffffffffu, x);
        if (lane == 0) sh[0] = x;
    }
    __syncthreads();
    return sh[0];
}

__global__ __launch_bounds__(NT)
void reward_fused_kernel(const int* __restrict__ chosen_ids,
                         const int* __restrict__ chosen_mask,
                         const int* __restrict__ rejected_ids,
                         const float* __restrict__ chosen_hidden,
                         const float* __restrict__ rejected_hidden,
                         const float* __restrict__ v_head_w,
                         float* __restrict__ out,
                         int B, int S, int H) {
    const int b   = blockIdx.x;
    const int tid = threadIdx.x;

    const int* cid = chosen_ids   + (size_t)b * S;
    const int* msk = chosen_mask  + (size_t)b * S;
    const int* rid = rejected_ids + (size_t)b * S;

    __shared__ int   sh_i[NT >> 5];
    __shared__ float sh_f[NT >> 5];
    __shared__ int   sh_last_flag;

    const int K = S / (NT * 4);
    const bool fast = ((S & (NT * 4 - 1)) == 0) && (K <= MAXK);

    int lc = S, lr = S, ldiv = 0;
    int start;

    if (fast) {
        // ---- one load burst: all three arrays into registers ----
        int4 mv[MAXK], cv[MAXK], rv[MAXK];
        #pragma unroll
        for (int k = 0; k < MAXK; k++) {
            if (k < K) {
                const int off = k * NT * 4 + tid * 4;
                mv[k] = *(const int4*)(msk + off);
                cv[k] = *(const int4*)(cid + off);
                rv[k] = *(const int4*)(rid + off);
            }
        }
        // first nonzero mask (descending assignment -> min index wins)
        int ls = S;
        #pragma unroll
        for (int k = MAXK - 1; k >= 0; k--) {
            if (k < K) {
                const int off = k * NT * 4 + tid * 4;
                if (mv[k].w) ls = off + 3;
                if (mv[k].z) ls = off + 2;
                if (mv[k].y) ls = off + 1;
                if (mv[k].x) ls = off;
            }
        }
        start = block_min_int(ls, sh_i);
        if (start == S) start = 0;         // argmax of all-false -> 0

        // first PAD (== 0) at position >= start, for both sequences; divergence flag
        #pragma unroll
        for (int k = MAXK - 1; k >= 0; k--) {
            if (k < K) {
                const int off = k * NT * 4 + tid * 4;
                ldiv |= (cv[k].x != rv[k].x) | (cv[k].y != rv[k].y) |
                        (cv[k].z != rv[k].z) | (cv[k].w != rv[k].w);
                if (cv[k].w == 0 && off + 3 >= start) lc = off + 3;
                if (cv[k].z == 0 && off + 2 >= start) lc = off + 2;
                if (cv[k].y == 0 && off + 1 >= start) lc = off + 1;
                if (cv[k].x == 0 && off     >= start) lc = off;
                if (rv[k].w == 0 && off + 3 >= start) lr = off + 3;
                if (rv[k].z == 0 && off + 2 >= start) lr = off + 2;
                if (rv[k].y == 0 && off + 1 >= start) lr = off + 1;
                if (rv[k].x == 0 && off     >= start) lr = off;
            }
        }
    } else {
        // ---- generic fallback ----
        int ls = S;
        for (int s = tid; s < S; s += NT)
            if (msk[s]) { ls = s; break; }   // strided ascending -> first hit is min
        start = block_min_int(ls, sh_i);
        if (start == S) start = 0;

        for (int s = tid; s < S; s += NT) {
            const int c = cid[s], r = rid[s];
            ldiv |= (c != r);
            if (s >= start) {
                if (c == 0 && s < lc) lc = s;
                if (r == 0 && s < lr) lr = s;
            }
        }
    }

    const int hasdiv = __syncthreads_or(ldiv);
    const int c_ind  = block_min_int(lc, sh_i);
    const int r_divi = block_min_int(lr, sh_i);
    const int r_ind  = hasdiv ? r_divi : c_ind;  // no-div: min(c_ind, S) == c_ind
    int last = min(c_ind, r_ind) - 1;
    if (last < 0) last += S;                      // JAX negative-index wrap

    // ---- dot products at the score position ----
    const float* ch = chosen_hidden   + ((size_t)b * S + last) * H;
    const float* rh = rejected_hidden + ((size_t)b * S + last) * H;

    float ac = 0.f, ar = 0.f;
    if ((H & 3) == 0) {
        for (int h = tid * 4; h < H; h += NT * 4) {
            const float4 w  = *(const float4*)(v_head_w + h);
            const float4 c4 = *(const float4*)(ch + h);
            const float4 r4 = *(const float4*)(rh + h);
            ac += c4.x * w.x + c4.y * w.y + c4.z * w.z + c4.w * w.w;
            ar += r4.x * w.x + r4.y * w.y + r4.z * w.z + r4.w * w.w;
        }
    } else {
        for (int h = tid; h < H; h += NT) {
            const float w = v_head_w[h];
            ac += ch[h] * w;
            ar += rh[h] * w;
        }
    }

    // block reduce both sums (warp shuffle + shared)
    #pragma unroll
    for (int o = 16; o; o >>= 1) {
        ac += __shfl_down_sync(0xffffffffu, ac, o);
        ar += __shfl_down_sync(0xffffffffu, ar, o);
    }
    const int warp = tid >> 5, lane = tid & 31;
    __shared__ float sh_f2[NT >> 5];
    __syncthreads();
    if (lane == 0) { sh_f[warp] = ac; sh_f2[warp] = ar; }
    __syncthreads();
    if (warp == 0) {
        float xc = (lane < (NT >> 5)) ? sh_f[lane]  : 0.f;
        float xr = (lane < (NT >> 5)) ? sh_f2[lane] : 0.f;
        #pragma unroll
        for (int o = 8; o; o >>= 1) {
            xc += __shfl_down_sync(0xffffffffu, xc, o);
            xr += __shfl_down_sync(0xffffffffu, xr, o);
        }
        if (lane == 0) {
            out[1 + b]     = xc;
            out[1 + B + b] = xr;
        }
    }

    // ---- arrival: last block computes the loss (no 2nd launch) ----
    if (tid == 0) {
        __threadfence();
        const int ticket = atomicAdd(&g_arrive, 1);
        sh_last_flag = (ticket == (int)gridDim.x - 1);
    }
    __syncthreads();
    if (sh_last_flag && tid < 32) {
        __threadfence();
        float v = 0.f;
        for (int i = tid; i < B; i += 32) {
            const float c = ((volatile float*)out)[1 + i];
            const float r = ((volatile float*)out)[1 + B + i];
            const float d = c - r;
            // -log_sigmoid(d) = softplus(-d), numerically stable
            v += fmaxf(-d, 0.f) + log1pf(expf(-fabsf(d)));
        }
        #pragma unroll
        for (int o = 16; o; o >>= 1) v += __shfl_down_sync(0xffffffffu, v, o);
        if (tid == 0) {
            out[0] = v / (float)B;
            atomicExch(&g_arrive, 0);   // reset for next graph replay
        }
    }
}

extern "C" void kernel_launch(void* const* d_in, const int* in_sizes, int n_in,
                              void* d_out, int out_size) {
    const int*   chosen_ids      = (const int*)  d_in[0];
    const int*   chosen_mask     = (const int*)  d_in[1];
    const int*   rejected_ids    = (const int*)  d_in[2];
    const float* chosen_hidden   = (const float*)d_in[3];
    const float* rejected_hidden = (const float*)d_in[4];
    const float* v_head_w        = (const float*)d_in[5];
    float*       out             = (float*)d_out;

    const int B = (out_size - 1) / 2;   // out = [loss, chosen(B), rejected(B)]
    const int S = in_sizes[0] / B;      // chosen_ids is [B,S]
    const int H = in_sizes[5];          // v_head_w is [H]

    reward_fused_kernel<<<B, NT>>>(chosen_ids, chosen_mask, rejected_ids,
                                   chosen_hidden, rejected_hidden, v_head_w,
                                   out, B, S, H);
}